// round 1
// baseline (speedup 1.0000x reference)
#include <cuda_runtime.h>
#include <cstdint>

// Problem constants (fixed-shape problem)
#define BATCH   4
#define NQ      2048
#define NP      8192
#define DIM     256
#define FBITS   40
#define KSEL    16
#define NCHUNK  4
#define CHUNK   (NP / NCHUNK)        // 2048

#define NQTOT   (BATCH * NQ)         // 8192
#define NPTOT   (BATCH * NP)         // 32768
#define NVEC    (NQTOT + NPTOT)      // 40960

// Scratch (device globals; no runtime allocation allowed)
__device__ uint2        g_codes[NVEC];                       // queries first, then points
__device__ unsigned int g_part[NQTOT * NCHUNK * KSEL];       // per-chunk top-16 packed keys

// ---------------------------------------------------------------------------
// Kernel 1: hash — 40 fp32 dot products per vector, sign -> 40-bit code
// Block: 128 threads = 4 warps; warp w handles projection rows [10w,10w+10),
// lane = vector (32 vectors per block). x tile XOR-swizzled in smem for
// conflict-free float4 reads; proj rows are broadcast reads.
// ---------------------------------------------------------------------------
#define HB  128
#define VPB 32

__global__ void __launch_bounds__(HB) hash_kernel(
    const float4* __restrict__ qv,     // [NQTOT][64] float4
    const float4* __restrict__ pv,     // [NPTOT][64] float4
    const float4* __restrict__ proj)   // [40][64] float4
{
    extern __shared__ float4 sm4[];
    float4*       ps     = sm4;                        // 40*64 float4
    float4*       xs     = sm4 + FBITS * 64;           // 32*64 float4 (swizzled)
    unsigned int* partsm = (unsigned int*)(sm4 + FBITS * 64 + VPB * 64); // 32*4 u32

    const int tid   = threadIdx.x;
    const int vbase = blockIdx.x * VPB;

    for (int i = tid; i < FBITS * 64; i += HB) ps[i] = proj[i];

    for (int fi = tid; fi < VPB * 64; fi += HB) {
        int v = fi >> 6, c = fi & 63;
        int vg = vbase + v;
        const float4* src = (vg < NQTOT) ? (qv + (size_t)vg * 64)
                                         : (pv + (size_t)(vg - NQTOT) * 64);
        xs[(v << 6) | (c ^ v)] = src[c];
    }
    __syncthreads();

    const int wq = tid >> 5;      // f-quarter 0..3
    const int v  = tid & 31;      // vector within block
    const int f0 = wq * 10;

    float4 acc[10];
#pragma unroll
    for (int j = 0; j < 10; j++) acc[j] = make_float4(0.f, 0.f, 0.f, 0.f);

#pragma unroll 4
    for (int d4 = 0; d4 < 64; d4++) {
        float4 xv = xs[(v << 6) | (d4 ^ v)];
#pragma unroll
        for (int j = 0; j < 10; j++) {
            float4 pj = ps[(f0 + j) * 64 + d4];
            acc[j].x += xv.x * pj.x;
            acc[j].y += xv.y * pj.y;
            acc[j].z += xv.z * pj.z;
            acc[j].w += xv.w * pj.w;
        }
    }

    unsigned int m = 0;
#pragma unroll
    for (int j = 0; j < 10; j++) {
        float s = (acc[j].x + acc[j].y) + (acc[j].z + acc[j].w);
        if (s > 0.0f) m |= (1u << j);
    }
    partsm[v * 4 + wq] = m;
    __syncthreads();

    if (tid < VPB) {
        unsigned int p0 = partsm[tid * 4 + 0];
        unsigned int p1 = partsm[tid * 4 + 1];
        unsigned int p2 = partsm[tid * 4 + 2];
        unsigned int p3 = partsm[tid * 4 + 3];
        unsigned int lo = p0 | (p1 << 10) | (p2 << 20) | (p3 << 30);
        unsigned int hi = p3 >> 2;   // bits 32..39
        g_codes[vbase + tid] = make_uint2(lo, hi);
    }
}

// ---------------------------------------------------------------------------
// Kernel 2: per-chunk exact top-16 via per-lane histogram (lane = query).
// Two passes over CHUNK point codes in smem (broadcast LDS.64):
//  pass 1: 41-bin per-lane smem histogram (stride 43 to spread banks)
//  prefix: exact threshold tau + count-below (nlt) per lane
//  pass 2: collect d<tau, plus first (16-nlt) with d==tau in INDEX ORDER
//          -> reproduces jax.lax.top_k stable tie-break exactly.
// Packed key = (d<<13)|global_point_idx; ascending key == (dist, idx) order.
// ---------------------------------------------------------------------------
#define TB   256
#define HSTR 43

__global__ void __launch_bounds__(TB) topk_kernel()
{
    extern __shared__ unsigned char smraw[];
    uint2*        spc   = (uint2*)smraw;                                   // CHUNK uint2
    unsigned int* shist = (unsigned int*)(smraw + CHUNK * sizeof(uint2));  // TB*HSTR u32

    const int tid   = threadIdx.x;
    const int b     = blockIdx.z;
    const int chunk = blockIdx.y;

    const uint2* pcod = g_codes + NQTOT + b * NP + chunk * CHUNK;
    for (int i = tid; i < CHUNK; i += TB) spc[i] = pcod[i];
    for (int i = tid; i < TB * HSTR; i += TB) shist[i] = 0u;
    __syncthreads();

    const int w    = tid >> 5;
    const int lane = tid & 31;
    const int q    = (blockIdx.x * 8 + w) * 32 + lane;
    const uint2 qc = g_codes[b * NQ + q];
    unsigned int* h = shist + tid * HSTR;

    // pass 1: histogram
#pragma unroll 4
    for (int i = 0; i < CHUNK; i++) {
        uint2 pc = spc[i];
        int d = __popc(qc.x ^ pc.x) + __popc(qc.y ^ pc.y);
        h[d] += 1u;
    }

    // prefix scan: find tau (16th order statistic) and nlt = #{d < tau}
    int cum = 0, tau = FBITS, nlt = 0, found = 0;
#pragma unroll
    for (int db = 0; db <= FBITS; db++) {
        int c  = (int)h[db];
        int c2 = cum + c;
        if (!found && c2 >= KSEL) { found = 1; tau = db; nlt = cum; }
        cum = c2;
    }
    const int quota = KSEL - nlt;

    // pass 2: collect exactly 16 keys in index order
    const unsigned int outbase =
        ((unsigned int)(b * NQ + q) * NCHUNK + (unsigned int)chunk) * KSEL;
    int cnt = 0, eq = 0;
#pragma unroll 4
    for (int i = 0; i < CHUNK; i++) {
        uint2 pc = spc[i];
        int d = __popc(qc.x ^ pc.x) + __popc(qc.y ^ pc.y);
        int t2   = (d == tau) & (eq < quota);
        eq += t2;
        int take = (d < tau) | t2;
        if (take) g_part[outbase + cnt] = ((unsigned int)d << 13)
                                        | (unsigned int)(chunk * CHUNK + i);
        cnt += take;
    }
}

// ---------------------------------------------------------------------------
// Kernel 3: merge 4 chunk-partials (64 unique keys) per query via rank count.
// rank r < 16 -> output slot r (globally sorted by (dist, idx)).
// Output layout: [0 .. 131071] = indices (as f32), [131072 ..] = distances.
// ---------------------------------------------------------------------------
__global__ void __launch_bounds__(256) merge_kernel(float* __restrict__ out)
{
    const int w    = threadIdx.x >> 5;
    const int lane = threadIdx.x & 31;
    const int qi   = blockIdx.x * 8 + w;            // 0..8191 (b*NQ+q)

    const unsigned int* basep = g_part + (size_t)qi * (NCHUNK * KSEL);
    unsigned int k0 = basep[lane];
    unsigned int k1 = basep[32 + lane];

    int r0 = 0, r1 = 0;
#pragma unroll
    for (int j = 0; j < 32; j++) {
        unsigned int a = __shfl_sync(0xffffffffu, k0, j);
        unsigned int c = __shfl_sync(0xffffffffu, k1, j);
        r0 += (a < k0) + (c < k0);
        r1 += (a < k1) + (c < k1);
    }
    if (r0 < KSEL) {
        out[(size_t)qi * KSEL + r0]               = (float)(k0 & (NP - 1));
        out[(size_t)NQTOT * KSEL + qi * KSEL + r0] = (float)(k0 >> 13);
    }
    if (r1 < KSEL) {
        out[(size_t)qi * KSEL + r1]               = (float)(k1 & (NP - 1));
        out[(size_t)NQTOT * KSEL + qi * KSEL + r1] = (float)(k1 >> 13);
    }
}

// ---------------------------------------------------------------------------
extern "C" void kernel_launch(void* const* d_in, const int* in_sizes, int n_in,
                              void* d_out, int out_size)
{
    const float4* qv   = (const float4*)d_in[0];
    const float4* pv   = (const float4*)d_in[1];
    const float4* proj = (const float4*)d_in[2];
    float* out = (float*)d_out;
    (void)in_sizes; (void)n_in; (void)out_size;

    const size_t hash_smem = (size_t)(FBITS * 64 + VPB * 64) * sizeof(float4)
                           + (size_t)VPB * 4 * sizeof(unsigned int);   // 74240 B
    const size_t topk_smem = (size_t)CHUNK * sizeof(uint2)
                           + (size_t)TB * HSTR * sizeof(unsigned int); // 60416 B

    cudaFuncSetAttribute(hash_kernel, cudaFuncAttributeMaxDynamicSharedMemorySize,
                         (int)hash_smem);
    cudaFuncSetAttribute(topk_kernel, cudaFuncAttributeMaxDynamicSharedMemorySize,
                         (int)topk_smem);

    hash_kernel<<<NVEC / VPB, HB, hash_smem>>>(qv, pv, proj);

    dim3 g2(NQ / (8 * 32), NCHUNK, BATCH);   // (8, 4, 4)
    topk_kernel<<<g2, TB, topk_smem>>>();

    merge_kernel<<<NQTOT / 8, 256>>>(out);
}

// round 2
// speedup vs baseline: 1.2325x; 1.2325x over previous
#include <cuda_runtime.h>
#include <cstdint>

// Problem constants (fixed-shape problem)
#define BATCH   4
#define NQ      2048
#define NP      8192
#define DIM     256
#define FBITS   40
#define KSEL    16
#define NCHUNK  16
#define CHUNK   (NP / NCHUNK)        // 512

#define NQTOT   (BATCH * NQ)         // 8192
#define NPTOT   (BATCH * NP)         // 32768
#define NVEC    (NQTOT + NPTOT)      // 40960

// Scratch (device globals; no runtime allocation allowed)
__device__ uint2        g_codes[NVEC];                       // queries first, then points
__device__ unsigned int g_part[NQTOT * NCHUNK * KSEL];       // per-chunk top-16 packed keys

// ---------------------------------------------------------------------------
// Kernel 1: hash — 40 fp32 dot products per vector, sign -> 40-bit code.
// Block: 256 threads; f-quarter wq = tid>>6 handles projection rows
// [10*wq, 10*wq+10); v = tid&63 selects one of 64 vectors per block.
// x rows are streamed straight from global (LDG.128, reuse=1 so no staging);
// proj lives in smem (40 KB) and is a pure warp-broadcast read.
// smem ~42 KB -> 5 blocks/SM -> 40 warps/SM.
// ---------------------------------------------------------------------------
#define HB  256
#define VPB 64

__global__ void __launch_bounds__(HB) hash_kernel(
    const float4* __restrict__ qv,     // [NQTOT][64] float4
    const float4* __restrict__ pv,     // [NPTOT][64] float4
    const float4* __restrict__ proj)   // [40][64] float4
{
    extern __shared__ float4 sm4[];
    float4*       ps     = sm4;                                  // 40*64 float4
    unsigned int* partsm = (unsigned int*)(sm4 + FBITS * 64);    // 64*4 u32

    const int tid   = threadIdx.x;
    const int vbase = blockIdx.x * VPB;

    for (int i = tid; i < FBITS * 64; i += HB) ps[i] = proj[i];
    __syncthreads();

    const int wq = tid >> 6;      // f-quarter 0..3
    const int v  = tid & 63;      // vector within block
    const int f0 = wq * 10;
    const int vg = vbase + v;

    const float4* __restrict__ xrow =
        (vg < NQTOT) ? (qv + (size_t)vg * 64) : (pv + (size_t)(vg - NQTOT) * 64);

    float4 acc[10];
#pragma unroll
    for (int j = 0; j < 10; j++) acc[j] = make_float4(0.f, 0.f, 0.f, 0.f);

#pragma unroll 4
    for (int d4 = 0; d4 < 64; d4++) {
        float4 xv = __ldg(xrow + d4);
#pragma unroll
        for (int j = 0; j < 10; j++) {
            float4 pj = ps[(f0 + j) * 64 + d4];
            acc[j].x += xv.x * pj.x;
            acc[j].y += xv.y * pj.y;
            acc[j].z += xv.z * pj.z;
            acc[j].w += xv.w * pj.w;
        }
    }

    unsigned int m = 0;
#pragma unroll
    for (int j = 0; j < 10; j++) {
        float s = (acc[j].x + acc[j].y) + (acc[j].z + acc[j].w);
        if (s > 0.0f) m |= (1u << j);
    }
    partsm[v * 4 + wq] = m;
    __syncthreads();

    if (tid < VPB) {
        unsigned int p0 = partsm[tid * 4 + 0];
        unsigned int p1 = partsm[tid * 4 + 1];
        unsigned int p2 = partsm[tid * 4 + 2];
        unsigned int p3 = partsm[tid * 4 + 3];
        unsigned int lo = p0 | (p1 << 10) | (p2 << 20) | (p3 << 30);
        unsigned int hi = p3 >> 2;   // bits 32..39
        g_codes[vbase + tid] = make_uint2(lo, hi);
    }
}

// ---------------------------------------------------------------------------
// Kernel 2: per-chunk exact top-16 via per-lane histogram (lane = query).
// Two passes over CHUNK point codes in smem (2 codes per LDS.128 broadcast):
//  pass 1: 41-bin per-lane smem histogram (stride 43 to spread banks)
//  prefix: exact threshold tau + count-below (nlt) per lane
//  pass 2: collect d<tau, plus first (16-nlt) with d==tau in INDEX ORDER
//          -> reproduces jax.lax.top_k stable tie-break exactly.
// Packed key = (d<<13)|global_point_idx; ascending key == (dist, idx) order.
// 512 blocks, smem ~47 KB -> ~3.5 blocks/SM resident.
// ---------------------------------------------------------------------------
#define TB   256
#define HSTR 43

__global__ void __launch_bounds__(TB) topk_kernel()
{
    extern __shared__ unsigned char smraw[];
    uint4*        spc   = (uint4*)smraw;                                   // CHUNK/2 uint4
    unsigned int* shist = (unsigned int*)(smraw + CHUNK * sizeof(uint2));  // TB*HSTR u32

    const int tid   = threadIdx.x;
    const int b     = blockIdx.z;
    const int chunk = blockIdx.y;

    const uint4* pcod = (const uint4*)(g_codes + NQTOT + b * NP + chunk * CHUNK);
    for (int i = tid; i < CHUNK / 2; i += TB) spc[i] = pcod[i];
    for (int i = tid; i < TB * HSTR; i += TB) shist[i] = 0u;
    __syncthreads();

    const int w    = tid >> 5;
    const int lane = tid & 31;
    const int q    = (blockIdx.x * 8 + w) * 32 + lane;
    const uint2 qc = g_codes[b * NQ + q];
    unsigned int* h = shist + tid * HSTR;

    // pass 1: histogram (2 points per smem load)
#pragma unroll 4
    for (int i = 0; i < CHUNK / 2; i++) {
        uint4 pc = spc[i];
        int d0 = __popc(qc.x ^ pc.x) + __popc(qc.y ^ pc.y);
        int d1 = __popc(qc.x ^ pc.z) + __popc(qc.y ^ pc.w);
        h[d0] += 1u;
        h[d1] += 1u;
    }

    // prefix scan: find tau (16th order statistic) and nlt = #{d < tau}
    int cum = 0, tau = FBITS, nlt = 0, found = 0;
#pragma unroll
    for (int db = 0; db <= FBITS; db++) {
        int c  = (int)h[db];
        int c2 = cum + c;
        if (!found && c2 >= KSEL) { found = 1; tau = db; nlt = cum; }
        cum = c2;
    }
    const int quota = KSEL - nlt;

    // pass 2: collect exactly 16 keys in index order
    const unsigned int outbase =
        ((unsigned int)(b * NQ + q) * NCHUNK + (unsigned int)chunk) * KSEL;
    int cnt = 0, eq = 0;
#pragma unroll 4
    for (int i = 0; i < CHUNK / 2; i++) {
        uint4 pc = spc[i];
        int d0 = __popc(qc.x ^ pc.x) + __popc(qc.y ^ pc.y);
        int d1 = __popc(qc.x ^ pc.z) + __popc(qc.y ^ pc.w);

        int t0   = (d0 == tau) & (eq < quota);
        eq += t0;
        int take0 = (d0 < tau) | t0;
        if (take0) g_part[outbase + cnt] = ((unsigned int)d0 << 13)
                                         | (unsigned int)(chunk * CHUNK + 2 * i);
        cnt += take0;

        int t1   = (d1 == tau) & (eq < quota);
        eq += t1;
        int take1 = (d1 < tau) | t1;
        if (take1) g_part[outbase + cnt] = ((unsigned int)d1 << 13)
                                         | (unsigned int)(chunk * CHUNK + 2 * i + 1);
        cnt += take1;
    }
}

// ---------------------------------------------------------------------------
// Kernel 3: merge 16 chunk-partials (256 unique keys) per query.
// One warp per query, 8 keys/lane; 16 rounds of (8-way local min ->
// __reduce_min_sync -> owner writes slot r and self-invalidates).
// Round r's global min is exactly the r-th smallest (dist, idx) pair.
// Output layout: [0 .. 131071] = indices (as f32), [131072 ..] = distances.
// ---------------------------------------------------------------------------
__global__ void __launch_bounds__(256) merge_kernel(float* __restrict__ out)
{
    const int w    = threadIdx.x >> 5;
    const int lane = threadIdx.x & 31;
    const int qi   = blockIdx.x * 8 + w;            // 0..8191 (b*NQ+q)

    const unsigned int* basep = g_part + (size_t)qi * (NCHUNK * KSEL);
    unsigned int k[8];
#pragma unroll
    for (int m = 0; m < 8; m++) k[m] = basep[m * 32 + lane];

    float* oidx = out + (size_t)qi * KSEL;
    float* odst = out + (size_t)NQTOT * KSEL + (size_t)qi * KSEL;

#pragma unroll
    for (int r = 0; r < KSEL; r++) {
        unsigned int loc = k[0];
#pragma unroll
        for (int m = 1; m < 8; m++) loc = min(loc, k[m]);
        unsigned int gmin = __reduce_min_sync(0xffffffffu, loc);
#pragma unroll
        for (int m = 0; m < 8; m++) {
            if (k[m] == gmin) {
                oidx[r] = (float)(gmin & (NP - 1));
                odst[r] = (float)(gmin >> 13);
                k[m] = 0xffffffffu;
            }
        }
    }
}

// ---------------------------------------------------------------------------
extern "C" void kernel_launch(void* const* d_in, const int* in_sizes, int n_in,
                              void* d_out, int out_size)
{
    const float4* qv   = (const float4*)d_in[0];
    const float4* pv   = (const float4*)d_in[1];
    const float4* proj = (const float4*)d_in[2];
    float* out = (float*)d_out;
    (void)in_sizes; (void)n_in; (void)out_size;

    const size_t hash_smem = (size_t)(FBITS * 64) * sizeof(float4)
                           + (size_t)VPB * 4 * sizeof(unsigned int);   // 41984 B
    const size_t topk_smem = (size_t)CHUNK * sizeof(uint2)
                           + (size_t)TB * HSTR * sizeof(unsigned int); // 48128 B

    cudaFuncSetAttribute(hash_kernel, cudaFuncAttributeMaxDynamicSharedMemorySize,
                         (int)hash_smem);
    cudaFuncSetAttribute(topk_kernel, cudaFuncAttributeMaxDynamicSharedMemorySize,
                         (int)topk_smem);

    hash_kernel<<<NVEC / VPB, HB, hash_smem>>>(qv, pv, proj);

    dim3 g2(NQ / (8 * 32), NCHUNK, BATCH);   // (8, 16, 4)
    topk_kernel<<<g2, TB, topk_smem>>>();

    merge_kernel<<<NQTOT / 8, 256>>>(out);
}

// round 5
// speedup vs baseline: 1.4056x; 1.1405x over previous
#include <cuda_runtime.h>
#include <cstdint>

// Problem constants (fixed-shape problem)
#define BATCH   4
#define NQ      2048
#define NP      8192
#define DIM     256
#define FBITS   40
#define KSEL    16
#define NCHUNK  16
#define CHUNK   (NP / NCHUNK)        // 512

#define NQTOT   (BATCH * NQ)         // 8192
#define NPTOT   (BATCH * NP)         // 32768
#define NVEC    (NQTOT + NPTOT)      // 40960

// Scratch (device globals; no runtime allocation allowed)
__device__ uint2        g_codes[NVEC];                       // queries first, then points
__device__ unsigned int g_part[NQTOT * NCHUNK * KSEL];       // per-chunk top-16 packed keys

// packed f32x2 FMA (PTX-only; 2x FFMA throughput on sm_103a)
__device__ __forceinline__ void ffma2(unsigned long long& d,
                                      unsigned long long a,
                                      unsigned long long b) {
    asm("fma.rn.f32x2 %0, %1, %2, %0;" : "+l"(d) : "l"(a), "l"(b));
}
__device__ __forceinline__ float2 unpack2(unsigned long long v) {
    float lo, hi;
    asm("mov.b64 {%0, %1}, %2;" : "=f"(lo), "=f"(hi) : "l"(v));
    return make_float2(lo, hi);
}

// ---------------------------------------------------------------------------
// Kernel 1: hash — 40 fp32 dot products per vector, sign -> 40-bit code.
// Block: 256 threads; f-quarter wq = tid>>6 handles projection rows
// [10*wq,10*wq+10); v = tid&63 is the vector within the block.
// x tile staged coalesced into smem with XOR swizzle (conflict-free LDS.128);
// proj in smem (warp-broadcast reads). FFMA2 packed math.
// smem ~105 KB -> 2 blocks/SM -> 16 warps/SM.
// ---------------------------------------------------------------------------
#define HB  256
#define VPB 64

__global__ void __launch_bounds__(HB) hash_kernel(
    const float4* __restrict__ qv,     // [NQTOT][64] float4
    const float4* __restrict__ pv,     // [NPTOT][64] float4
    const float4* __restrict__ proj)   // [40][64] float4
{
    extern __shared__ float4 sm4[];
    float4*       ps     = sm4;                                  // 40*64 float4
    float4*       xs     = sm4 + FBITS * 64;                     // 64*64 float4 (swizzled)
    unsigned int* partsm = (unsigned int*)(sm4 + FBITS * 64 + VPB * 64); // 64*4 u32

    const int tid   = threadIdx.x;
    const int vbase = blockIdx.x * VPB;

    for (int i = tid; i < FBITS * 64; i += HB) ps[i] = proj[i];

    for (int fi = tid; fi < VPB * 64; fi += HB) {
        int v = fi >> 6, c = fi & 63;
        int vg = vbase + v;
        const float4* src = (vg < NQTOT) ? (qv + (size_t)vg * 64)
                                         : (pv + (size_t)(vg - NQTOT) * 64);
        xs[(v << 6) | (c ^ v)] = src[c];
    }
    __syncthreads();

    const int wq = tid >> 6;      // f-quarter 0..3 (uniform per warp)
    const int v  = tid & 63;      // vector within block
    const int f0 = wq * 10;

    unsigned long long accl[10], acch[10];
#pragma unroll
    for (int j = 0; j < 10; j++) { accl[j] = 0ull; acch[j] = 0ull; }

#pragma unroll 4
    for (int d4 = 0; d4 < 64; d4++) {
        const ulonglong2 xv =
            *reinterpret_cast<const ulonglong2*>(&xs[(v << 6) | (d4 ^ v)]);
#pragma unroll
        for (int j = 0; j < 10; j++) {
            const ulonglong2 pj =
                *reinterpret_cast<const ulonglong2*>(&ps[(f0 + j) * 64 + d4]);
            ffma2(accl[j], xv.x, pj.x);
            ffma2(acch[j], xv.y, pj.y);
        }
    }

    unsigned int m = 0;
#pragma unroll
    for (int j = 0; j < 10; j++) {
        float2 lo = unpack2(accl[j]);   // (x, y)
        float2 hi = unpack2(acch[j]);   // (z, w)
        float s = (lo.x + lo.y) + (hi.x + hi.y);
        if (s > 0.0f) m |= (1u << j);
    }
    partsm[v * 4 + wq] = m;
    __syncthreads();

    if (tid < VPB) {
        unsigned int p0 = partsm[tid * 4 + 0];
        unsigned int p1 = partsm[tid * 4 + 1];
        unsigned int p2 = partsm[tid * 4 + 2];
        unsigned int p3 = partsm[tid * 4 + 3];
        unsigned int lo = p0 | (p1 << 10) | (p2 << 20) | (p3 << 30);
        unsigned int hi = p3 >> 2;   // bits 32..39
        g_codes[vbase + tid] = make_uint2(lo, hi);
    }
}

// ---------------------------------------------------------------------------
// Kernel 2: per-chunk exact top-16 via per-lane histogram (lane = query).
// Dual u16 histogram arrays per thread (even point -> A, odd point -> B):
// breaks the LDS->IADD->STS dependency chain into two independent chains.
// Per-thread region = 43 words (86 halfwords, A at [0..41), B at [41..82));
// stride 43 words is odd -> conflict-free across the warp.
//  pass 1: dual histogram
//  prefix: exact threshold tau + count-below (nlt), c = A[d]+B[d]
//  pass 2: collect d<tau, plus first (16-nlt) with d==tau in INDEX ORDER
//          -> reproduces jax.lax.top_k stable tie-break exactly.
// Packed key = (d<<13)|global_point_idx; ascending key == (dist, idx) order.
// ---------------------------------------------------------------------------
#define TB   256
#define HWPT 43   // hist words per thread

__global__ void __launch_bounds__(TB) topk_kernel()
{
    extern __shared__ unsigned char smraw[];
    uint4*          spc = (uint4*)smraw;                                   // CHUNK/2 uint4
    unsigned short* sh  = (unsigned short*)(smraw + CHUNK * sizeof(uint2));
    unsigned int*   shw = (unsigned int*)sh;                               // TB*HWPT u32

    const int tid   = threadIdx.x;
    const int b     = blockIdx.z;
    const int chunk = blockIdx.y;

    const uint4* pcod = (const uint4*)(g_codes + NQTOT + b * NP + chunk * CHUNK);
    for (int i = tid; i < CHUNK / 2; i += TB) spc[i] = pcod[i];
    for (int i = tid; i < TB * HWPT; i += TB) shw[i] = 0u;
    __syncthreads();

    const int w    = tid >> 5;
    const int lane = tid & 31;
    const int q    = (blockIdx.x * 8 + w) * 32 + lane;
    const uint2 qc = g_codes[b * NQ + q];

    unsigned short* hA = sh + tid * (2 * HWPT);
    unsigned short* hB = hA + 41;

    // pass 1: dual histogram (2 points per smem load, independent chains)
#pragma unroll 8
    for (int i = 0; i < CHUNK / 2; i++) {
        uint4 pc = spc[i];
        int d0 = __popc(qc.x ^ pc.x) + __popc(qc.y ^ pc.y);
        int d1 = __popc(qc.x ^ pc.z) + __popc(qc.y ^ pc.w);
        hA[d0] = (unsigned short)(hA[d0] + 1u);
        hB[d1] = (unsigned short)(hB[d1] + 1u);
    }

    // prefix scan: find tau (16th order statistic) and nlt = #{d < tau}
    int cum = 0, tau = FBITS, nlt = 0, found = 0;
#pragma unroll
    for (int db = 0; db <= FBITS; db++) {
        int c  = (int)hA[db] + (int)hB[db];
        int c2 = cum + c;
        if (!found && c2 >= KSEL) { found = 1; tau = db; nlt = cum; }
        cum = c2;
    }
    const int quota = KSEL - nlt;

    // pass 2: collect exactly 16 keys in index order
    const unsigned int outbase =
        ((unsigned int)(b * NQ + q) * NCHUNK + (unsigned int)chunk) * KSEL;
    const unsigned int ibase = (unsigned int)(chunk * CHUNK);
    int cnt = 0, eq = 0;
#pragma unroll 8
    for (int i = 0; i < CHUNK / 2; i++) {
        uint4 pc = spc[i];
        int d0 = __popc(qc.x ^ pc.x) + __popc(qc.y ^ pc.y);
        int d1 = __popc(qc.x ^ pc.z) + __popc(qc.y ^ pc.w);

        int t0   = (d0 == tau) & (eq < quota);
        eq += t0;
        int take0 = (d0 < tau) | t0;
        if (take0) g_part[outbase + cnt] = ((unsigned int)d0 << 13)
                                         | (ibase + 2 * i);
        cnt += take0;

        int t1   = (d1 == tau) & (eq < quota);
        eq += t1;
        int take1 = (d1 < tau) | t1;
        if (take1) g_part[outbase + cnt] = ((unsigned int)d1 << 13)
                                         | (ibase + 2 * i + 1);
        cnt += take1;
    }
}

// ---------------------------------------------------------------------------
// Kernel 3: merge 16 chunk-partials (256 unique keys) per query.
// One warp per query, 8 keys/lane; 16 rounds of (8-way local min ->
// __reduce_min_sync -> owner writes slot r and self-invalidates).
// Round r's global min is exactly the r-th smallest (dist, idx) pair.
// Output layout: [0 .. 131071] = indices (as f32), [131072 ..] = distances.
// ---------------------------------------------------------------------------
__global__ void __launch_bounds__(256) merge_kernel(float* __restrict__ out)
{
    const int w    = threadIdx.x >> 5;
    const int lane = threadIdx.x & 31;
    const int qi   = blockIdx.x * 8 + w;            // 0..8191 (b*NQ+q)

    const unsigned int* basep = g_part + (size_t)qi * (NCHUNK * KSEL);
    unsigned int k[8];
#pragma unroll
    for (int m = 0; m < 8; m++) k[m] = basep[m * 32 + lane];

    float* oidx = out + (size_t)qi * KSEL;
    float* odst = out + (size_t)NQTOT * KSEL + (size_t)qi * KSEL;

#pragma unroll
    for (int r = 0; r < KSEL; r++) {
        unsigned int loc = k[0];
#pragma unroll
        for (int m = 1; m < 8; m++) loc = min(loc, k[m]);
        unsigned int gmin = __reduce_min_sync(0xffffffffu, loc);
#pragma unroll
        for (int m = 0; m < 8; m++) {
            if (k[m] == gmin) {
                oidx[r] = (float)(gmin & (NP - 1));
                odst[r] = (float)(gmin >> 13);
                k[m] = 0xffffffffu;
            }
        }
    }
}

// ---------------------------------------------------------------------------
extern "C" void kernel_launch(void* const* d_in, const int* in_sizes, int n_in,
                              void* d_out, int out_size)
{
    const float4* qv   = (const float4*)d_in[0];
    const float4* pv   = (const float4*)d_in[1];
    const float4* proj = (const float4*)d_in[2];
    float* out = (float*)d_out;
    (void)in_sizes; (void)n_in; (void)out_size;

    const size_t hash_smem = (size_t)(FBITS * 64 + VPB * 64) * sizeof(float4)
                           + (size_t)VPB * 4 * sizeof(unsigned int);   // 107520 B
    const size_t topk_smem = (size_t)CHUNK * sizeof(uint2)
                           + (size_t)TB * HWPT * sizeof(unsigned int); // 48128 B

    cudaFuncSetAttribute(hash_kernel, cudaFuncAttributeMaxDynamicSharedMemorySize,
                         (int)hash_smem);
    cudaFuncSetAttribute(topk_kernel, cudaFuncAttributeMaxDynamicSharedMemorySize,
                         (int)topk_smem);

    hash_kernel<<<NVEC / VPB, HB, hash_smem>>>(qv, pv, proj);

    dim3 g2(NQ / (8 * 32), NCHUNK, BATCH);   // (8, 16, 4)
    topk_kernel<<<g2, TB, topk_smem>>>();

    merge_kernel<<<NQTOT / 8, 256>>>(out);
}